// round 1
// baseline (speedup 1.0000x reference)
#include <cuda_runtime.h>
#include <math.h>

namespace {
constexpr int Bn = 8, Cn = 4, Hn = 256, Wn = 256;
constexpr int NPIX = Bn * Hn * Wn;  // 524288
}

__device__ double g_acc;
__device__ int g_is64;

// Load mask element idx, handling int32 vs int64 storage (little-endian:
// int64 value 0..3 lives in the low 32-bit word at 2*idx).
__device__ __forceinline__ int ld_mask(const int* __restrict__ m, int idx, int is64) {
    return __ldg(m + (idx << is64));
}

// Exact vertical 1D distance at (h, w) for class c: smallest k>=1 with a
// background pixel (mask != c) at h-k or h+k; matches the reference's
// min(d_up, d_down, BIG=512) for a foreground pixel.
__device__ __forceinline__ int vdist(const int* __restrict__ m, int base,
                                     int h, int w, int c, int is64) {
#pragma unroll 1
    for (int k = 1; k < Hn; ++k) {
        int up = h - k, dn = h + k;
        bool hit = false;
        if (up >= 0) hit = (ld_mask(m, base + up * Wn + w, is64) != c);
        if (dn < Hn) hit = hit || (ld_mask(m, base + dn * Wn + w, is64) != c);
        if (hit) return k;
        if (up <= 0 && dn >= Hn - 1) return 512;  // no background in column
    }
    return 512;
}

__global__ void init_kernel(const int* __restrict__ mask) {
    if (blockIdx.x == 0 && threadIdx.x == 0) {
        g_acc = 0.0;
        // int64 detection: values are 0..3, so for int64 storage every odd
        // 32-bit word is zero. 256 words checked -> false-positive prob 4^-256.
        int all_zero = 1;
        for (int i = 0; i < 256; ++i) {
            if (mask[2 * i + 1] != 0) { all_zero = 0; break; }
        }
        g_is64 = all_zero;
    }
}

__global__ void boundary_loss_kernel(const float* __restrict__ pred,
                                     const int* __restrict__ mask) {
    const int tid = blockIdx.x * blockDim.x + threadIdx.x;  // 0..NPIX-1
    const int w = tid & (Wn - 1);
    const int h = (tid >> 8) & (Hn - 1);
    const int b = tid >> 16;
    const int is64 = g_is64;
    const int base = b * (Hn * Wn);

    float term = 0.0f;
    const int c = ld_mask(mask, base + h * Wn + w, is64);
    if (c != 0) {
        // Candidate x' = x: vertical distance squared at own column.
        int g0 = vdist(mask, base, h, w, c, is64);
        float m = (float)(g0 * g0);

        // Exact lower-envelope min with outward pruning: remaining candidates
        // at radius r have value >= r*r, so stop when r*r >= m.
#pragma unroll 1
        for (int r = 1; r < Wn; ++r) {
            float r2 = (float)(r * r);
            if (r2 >= m) break;
            int xl = w - r, xr = w + r;
            if (xl < 0 && xr >= Wn) break;
            if (xl >= 0) {
                float g2p = 0.0f;
                if (ld_mask(mask, base + h * Wn + xl, is64) == c) {
                    int gv = vdist(mask, base, h, xl, c, is64);
                    g2p = (float)(gv * gv);
                }
                m = fminf(m, g2p + r2);
            }
            if (xr < Wn) {
                float g2p = 0.0f;
                if (ld_mask(mask, base + h * Wn + xr, is64) == c) {
                    int gv = vdist(mask, base, h, xr, c, is64);
                    g2p = (float)(gv * gv);
                }
                m = fminf(m, g2p + r2);
            }
        }

        const float norm = (float)(sqrt((double)(Hn * Hn + Wn * Wn)) + 1e-6);
        float dist = sqrtf(m) / norm;
        term = __ldg(&pred[((b * Cn + c) * Hn + h) * Wn + w]) * dist;
    }

    // Block reduction: warp shuffle + shared, then one double atomic per block.
#pragma unroll
    for (int o = 16; o > 0; o >>= 1)
        term += __shfl_down_sync(0xFFFFFFFFu, term, o);

    __shared__ float ws[8];
    if ((threadIdx.x & 31) == 0) ws[threadIdx.x >> 5] = term;
    __syncthreads();
    if (threadIdx.x < 8) {
        float v = ws[threadIdx.x];
#pragma unroll
        for (int o = 4; o > 0; o >>= 1)
            v += __shfl_down_sync(0xFFu, v, o);
        if (threadIdx.x == 0) atomicAdd(&g_acc, (double)v);
    }
}

__global__ void finalize_kernel(float* __restrict__ out, int n) {
    float v = (float)(g_acc / ((double)NPIX * (Cn - 1)));
    for (int i = threadIdx.x; i < n; i += blockDim.x) out[i] = v;
}

extern "C" void kernel_launch(void* const* d_in, const int* in_sizes, int n_in,
                              void* d_out, int out_size) {
    // Identify inputs by element count: pred_softmax has 4x the elements of mask.
    const float* pred;
    const int* mask;
    if (in_sizes[0] >= in_sizes[1]) {
        pred = (const float*)d_in[0];
        mask = (const int*)d_in[1];
    } else {
        pred = (const float*)d_in[1];
        mask = (const int*)d_in[0];
    }

    init_kernel<<<1, 32>>>(mask);
    boundary_loss_kernel<<<NPIX / 256, 256>>>(pred, mask);
    finalize_kernel<<<1, 32>>>((float*)d_out, out_size);
}